// round 13
// baseline (speedup 1.0000x reference)
#include <cuda_runtime.h>
#include <cuda_fp16.h>
#include <stdint.h>
#include <math.h>

#define BATCH 16384
#define DIM   1024
#define FFN   4096

#define NB ((size_t)BATCH * DIM)
#define NF ((size_t)BATCH * FFN)

// ---------------- scratch (static device globals; no runtime allocs) -------
__device__ __half g_modsh[3 * NB];                     // m0|m1|m2 fp16, stacked [3B,1024]
__device__ __half g_Aq[(size_t)BATCH * 2 * DIM];       // [B, 2048] = [mavg | dom] fp16
__device__ __half g_Bq[(size_t)DIM * 2 * DIM];         // [1024, 2048] = [Wgq^T | Wq^T] fp16
__device__ __half g_qh[NB];
__device__ __half g_kvh[3 * (size_t)BATCH * 2 * DIM];  // [3B, 2048]: k|v
__device__ __half g_xh[NB];
__device__ __half g_h1h[NF];
__device__ __half g_Wkvth[(size_t)2*DIM*DIM];          // Wk^T rows 0..1023, Wv^T rows 1024..2047
__device__ __half g_W1th[(size_t)DIM*FFN];
__device__ __half g_W2th[(size_t)DIM*FFN];
__device__ __half g_Wgf[(size_t)DIM*DIM];              // Wg fp16, NO transpose
__device__ float  g_bkv[2 * DIM];
__device__ float  g_bq2[DIM];
__device__ float  g_zb[DIM];                           // zero bias (zero-initialized)
__device__ float  g_y[NB];                             // y0 = LN1(x)+b2, then += FFN2 partials

// ---------------- helpers ----------------------------------------------------
__device__ __forceinline__ uint32_t s2u(const void* p) {
    uint32_t a;
    asm("{ .reg .u64 t; cvta.to.shared.u64 t, %1; cvt.u32.u64 %0, t; }" : "=r"(a) : "l"(p));
    return a;
}
__device__ __forceinline__ void cp16(uint32_t s, const void* g) {
    asm volatile("cp.async.cg.shared.global [%0], [%1], 16;" :: "r"(s), "l"(g));
}
#define SWZ(o) ((o) ^ (((o) >> 3) & 0x70))

__device__ __forceinline__ void ldsm4(uint32_t addr, uint32_t* r) {
    asm volatile("ldmatrix.sync.aligned.m8n8.x4.shared.b16 {%0,%1,%2,%3}, [%4];"
        : "=r"(r[0]), "=r"(r[1]), "=r"(r[2]), "=r"(r[3]) : "r"(addr));
}
__device__ __forceinline__ void mma16816(float* c, const uint32_t* a, const uint32_t* b) {
    asm volatile(
        "mma.sync.aligned.m16n8k16.row.col.f32.f16.f16.f32 "
        "{%0,%1,%2,%3}, {%4,%5,%6,%7}, {%8,%9}, {%0,%1,%2,%3};"
        : "+f"(c[0]), "+f"(c[1]), "+f"(c[2]), "+f"(c[3])
        : "r"(a[0]), "r"(a[1]), "r"(a[2]), "r"(a[3]), "r"(b[0]), "r"(b[1]));
}
__device__ __forceinline__ void redadd(float* p, float v) {
    asm volatile("red.global.add.f32 [%0], %1;" :: "l"(p), "f"(v) : "memory");
}

// ---------------- GEMM body (128x128 CTA, 32x64 warp tiles) ------------------
#define STAGE_SZ 32768
#define SMEM_SZ  (3 * STAGE_SZ)

__device__ __forceinline__ void ldtile(uint32_t sbase, const __half* g, int ldk, int tid) {
    #pragma unroll
    for (int i = 0; i < 4; i++) {
        int idx = tid + (i << 8);
        int row = idx >> 3, ks = idx & 7;
        cp16(sbase + SWZ(row * 128 + ks * 16), g + (size_t)row * ldk + ks * 8);
    }
}

// MODE 0: +bias; MODE 2: relu(+bias); MODE 3: atomic add fp32 (no bias)
// CVT: write fp16.
template<int MODE, bool CVT>
__device__ __forceinline__ void gemm_body(
    const __half* __restrict__ A, const __half* __restrict__ B,
    const float* __restrict__ bias,
    float* __restrict__ Dout, __half* __restrict__ Dh,
    int bm, int bn, int K, int lda, int ldb, int ldd, uint32_t sb)
{
    const int tid = threadIdx.x;
    const int wid = tid >> 5, lane = tid & 31;
    const int wm = (wid >> 1) << 5;
    const int wn = (wid & 1) << 6;
    const int nch = K >> 6;

    const __half* Ap = A + (size_t)bm * lda;
    const __half* Bp = B + (size_t)bn * ldb;

    #pragma unroll
    for (int c = 0; c < 2; c++) {
        uint32_t st = sb + c * STAGE_SZ;
        ldtile(st,         Ap + c * 64, lda, tid);
        ldtile(st + 16384, Bp + c * 64, ldb, tid);
        asm volatile("cp.async.commit_group;" ::: "memory");
    }

    float acc[2][8][4];
    #pragma unroll
    for (int a = 0; a < 2; a++)
        #pragma unroll
        for (int b2 = 0; b2 < 8; b2++)
            #pragma unroll
            for (int d = 0; d < 4; d++) acc[a][b2][d] = 0.0f;

    const int aRow = wm + (lane & 15);
    const int aKB  = ((lane >> 4) & 1) * 16;
    const int bj   = lane >> 3;
    const int bRow = wn + ((bj >> 1) << 3) + (lane & 7);
    const int bKB  = (bj & 1) * 16;

    for (int i = 0; i < nch; i++) {
        if (i < nch - 1) asm volatile("cp.async.wait_group 1;" ::: "memory");
        else             asm volatile("cp.async.wait_group 0;" ::: "memory");
        __syncthreads();

        const int pc = i + 2;
        if (pc < nch) {
            uint32_t pt = sb + (pc % 3) * STAGE_SZ;
            ldtile(pt,         Ap + pc * 64, lda, tid);
            ldtile(pt + 16384, Bp + pc * 64, ldb, tid);
            asm volatile("cp.async.commit_group;" ::: "memory");
        }

        const uint32_t st = sb + (i % 3) * STAGE_SZ;
        #pragma unroll
        for (int kk = 0; kk < 4; kk++) {
            uint32_t aR[2][4];
            #pragma unroll
            for (int tm = 0; tm < 2; tm++) {
                uint32_t off = SWZ((uint32_t)((aRow + tm * 16) * 128 + kk * 32 + aKB));
                ldsm4(st + off, aR[tm]);
            }
            uint32_t bR[4][4];
            #pragma unroll
            for (int p = 0; p < 4; p++) {
                uint32_t off = SWZ((uint32_t)((bRow + p * 16) * 128 + kk * 32 + bKB));
                ldsm4(st + 16384 + off, bR[p]);
            }
            #pragma unroll
            for (int tm = 0; tm < 2; tm++)
                #pragma unroll
                for (int p = 0; p < 4; p++) {
                    mma16816(acc[tm][2*p],     aR[tm], &bR[p][0]);
                    mma16816(acc[tm][2*p + 1], aR[tm], &bR[p][2]);
                }
        }
    }

    const int lm = lane >> 2, lc = (lane & 3) << 1;
    float2 bs[8];
    if (MODE != 3) {
        #pragma unroll
        for (int nt = 0; nt < 8; nt++)
            bs[nt] = *(const float2*)(bias + bn + wn + nt * 8 + lc);
    }

    #pragma unroll
    for (int tm = 0; tm < 2; tm++)
        #pragma unroll
        for (int g = 0; g < 2; g++) {
            const int row = bm + wm + tm * 16 + g * 8 + lm;
            #pragma unroll
            for (int nt = 0; nt < 8; nt++) {
                const int col = bn + wn + nt * 8 + lc;
                float v0 = acc[tm][nt][g * 2 + 0];
                float v1 = acc[tm][nt][g * 2 + 1];
                if (MODE == 3) {
                    float* p = Dout + (size_t)row * ldd + col;
                    redadd(p, v0);
                    redadd(p + 1, v1);
                    continue;
                }
                v0 += bs[nt].x; v1 += bs[nt].y;
                if (MODE == 2) { v0 = fmaxf(v0, 0.f); v1 = fmaxf(v1, 0.f); }
                if (CVT)
                    *(__half2*)(Dh + (size_t)row * ldd + col) = __floats2half2_rn(v0, v1);
                else
                    *(float2*)(Dout + (size_t)row * ldd + col) = make_float2(v0, v1);
            }
        }
}

template<int MODE, bool CVT>
__global__ __launch_bounds__(256, 2)
void mma_gemm(const __half* __restrict__ A, const __half* __restrict__ B,
              const float* __restrict__ bias,
              float* __restrict__ Dout, __half* __restrict__ Dh,
              int K, int lda, int ldb, int ldd)
{
    extern __shared__ char smem[];
    gemm_body<MODE, CVT>(A, B, bias, Dout, Dh,
                         blockIdx.y << 7, blockIdx.x << 7, K, lda, ldb, ldd, s2u(smem));
}

// merged q-GEMM (blocks 0..1023) + kv-GEMM (blocks 1024..7167)
__global__ __launch_bounds__(256, 2)
void qkv_gemm(const __half* __restrict__ Aq, const __half* __restrict__ Bq,
              const float* __restrict__ bq2, __half* __restrict__ qh,
              const __half* __restrict__ mods, const __half* __restrict__ Wkv,
              const float* __restrict__ bkv, __half* __restrict__ kvh)
{
    extern __shared__ char smem[];
    uint32_t sb = s2u(smem);
    int b = blockIdx.x;
    if (b < 1024) {
        gemm_body<0, true>(Aq, Bq, bq2, nullptr, qh,
                           (b >> 3) << 7, (b & 7) << 7, 2048, 2048, 2048, 1024, sb);
    } else {
        b -= 1024;
        gemm_body<0, true>(mods, Wkv, bkv, nullptr, kvh,
                           (b >> 4) << 7, (b & 15) << 7, 1024, 1024, 1024, 2048, sb);
    }
}

// FFN2 split-K: 2048 CTAs, K halves of 2048, atomic-accumulate into y
__global__ __launch_bounds__(256, 2)
void ffn2_gemm(const __half* __restrict__ h1, const __half* __restrict__ W2t,
               float* __restrict__ y)
{
    extern __shared__ char smem[];
    int b = blockIdx.x;
    const int kp = b >> 10;          // 0 or 1
    b &= 1023;
    gemm_body<3, false>(h1 + (size_t)kp * 2048, W2t + (size_t)kp * 2048, nullptr,
                        y, nullptr,
                        (b >> 3) << 7, (b & 7) << 7, 2048, FFN, FFN, DIM, s2u(smem));
}

// ---------------- fused prep: activations + all weight prep ------------------
__device__ __forceinline__ void wtrans_body(const float* __restrict__ W, __half* __restrict__ H,
                                            int N, int ldh, int bx, int by,
                                            float (*t)[33], int tx, int ty)
{
    const int k0 = by << 5, n0 = bx << 5;
    #pragma unroll
    for (int r = 0; r < 32; r += 8)
        t[ty + r][tx] = W[(size_t)(k0 + ty + r) * N + n0 + tx];
    __syncthreads();
    #pragma unroll
    for (int r = 0; r < 32; r += 8)
        H[(size_t)(n0 + ty + r) * ldh + k0 + tx] = __float2half(t[tx][ty + r]);
}

__global__ __launch_bounds__(256)
void prep_all(const float4* __restrict__ m0, const float4* __restrict__ m1,
              const float4* __restrict__ m2, const float4* __restrict__ dom,
              const float* __restrict__ Wq, const float* __restrict__ Wk,
              const float* __restrict__ Wv, const float* __restrict__ W1f,
              const float* __restrict__ W2f, const float* __restrict__ Wg,
              const float* __restrict__ bk, const float* __restrict__ bv,
              const float* __restrict__ bg, const float* __restrict__ bq,
              __half* __restrict__ mods, __half* __restrict__ Aq, __half* __restrict__ Bq,
              __half* __restrict__ Wkvth, __half* __restrict__ W1th, __half* __restrict__ W2th,
              __half* __restrict__ Wgf, float* __restrict__ bkv, float* __restrict__ bq2)
{
    __shared__ float t[32][33];
    const int b = blockIdx.x;
    const int tid = threadIdx.x;
    const int tx = tid & 31, ty = tid >> 5;

    if (b < 16384) {
        const int i = b * 256 + tid;
        float4 a = m0[i], bb = m1[i], c = m2[i], d = dom[i];
        const float s = 1.0f / 3.0f;
        const int r = i >> 8, c4 = (i & 255) << 2;
        const size_t nbh = NB;
        __half2* modsp = (__half2*)mods;
        modsp[(0*nbh + (size_t)r*1024 + c4) >> 1]       = __floats2half2_rn(a.x, a.y);
        modsp[((0*nbh + (size_t)r*1024 + c4) >> 1) + 1] = __floats2half2_rn(a.z, a.w);
        modsp[(1*nbh + (size_t)r*1024 + c4) >> 1]       = __floats2half2_rn(bb.x, bb.y);
        modsp[((1*nbh + (size_t)r*1024 + c4) >> 1) + 1] = __floats2half2_rn(bb.z, bb.w);
        modsp[(2*nbh + (size_t)r*1024 + c4) >> 1]       = __floats2half2_rn(c.x, c.y);
        modsp[((2*nbh + (size_t)r*1024 + c4) >> 1) + 1] = __floats2half2_rn(c.z, c.w);
        float4 v;
        v.x = (a.x+bb.x+c.x)*s; v.y = (a.y+bb.y+c.y)*s;
        v.z = (a.z+bb.z+c.z)*s; v.w = (a.w+bb.w+c.w)*s;
        __half2* aqp = (__half2*)(Aq + (size_t)r * 2048 + c4);
        aqp[0] = __floats2half2_rn(v.x, v.y);
        aqp[1] = __floats2half2_rn(v.z, v.w);
        __half2* aqd = (__half2*)(Aq + (size_t)r * 2048 + 1024 + c4);
        aqd[0] = __floats2half2_rn(d.x, d.y);
        aqd[1] = __floats2half2_rn(d.z, d.w);
    } else if (b < 17408) {
        int bl = b - 16384;
        wtrans_body(Wq, Bq + 1024, DIM, 2048, bl & 31, bl >> 5, t, tx, ty);
    } else if (b < 18432) {
        int bl = b - 17408;
        wtrans_body(Wk, Wkvth, DIM, DIM, bl & 31, bl >> 5, t, tx, ty);
    } else if (b < 19456) {
        int bl = b - 18432;
        wtrans_body(Wv, Wkvth + (size_t)DIM * DIM, DIM, DIM, bl & 31, bl >> 5, t, tx, ty);
    } else if (b < 23552) {
        int bl = b - 19456;
        wtrans_body(W1f, W1th, FFN, DIM, bl & 127, bl >> 7, t, tx, ty);
    } else if (b < 27648) {
        int bl = b - 23552;
        wtrans_body(W2f, W2th, DIM, FFN, bl & 31, bl >> 5, t, tx, ty);
    } else if (b < 28672) {
        int i = (b - 27648) * 1024 + tid * 4;
        float4 w = *(const float4*)(Wg + i);
        __half2* o = (__half2*)(Wgf + i);
        o[0] = __floats2half2_rn(w.x, w.y);
        o[1] = __floats2half2_rn(w.z, w.w);
    } else if (b < 28680) {
        int i = (b - 28672) * 256 + tid;
        bkv[i]       = bk[i];
        bkv[i + DIM] = bv[i];
    } else {
        int n = b - 28680;
        float s = 0.f;
        for (int k = tid; k < DIM; k += 256) s += bg[k] * Wq[(size_t)k * DIM + n];
        #pragma unroll
        for (int o = 16; o; o >>= 1) s += __shfl_xor_sync(0xffffffffu, s, o);
        float* red = &t[0][0];
        if ((tid & 31) == 0) red[tid >> 5] = s;
        __syncthreads();
        if (tid == 0) {
            float a = 0.f;
            #pragma unroll
            for (int i = 0; i < 8; i++) a += red[i];
            bq2[n] = a + bq[n];
        }
    }
}

// ---------------- attention + residual + LN1 (block-per-row, R11) ------------
__global__ __launch_bounds__(256)
void attn_ln1_kernel(const __half2* __restrict__ qh,
                     const __half* __restrict__ kvh,
                     const __half* __restrict__ Aqdom,
                     const float* __restrict__ gam, const float* __restrict__ bet,
                     const float* __restrict__ b2,
                     float* __restrict__ y, __half2* __restrict__ xh)
{
    const int b = blockIdx.x;
    const int t = threadIdx.x;
    const size_t off = (size_t)b * DIM + 4 * t;

    float2 qa = __half22float2(qh[off/2]);
    float2 qb = __half22float2(qh[off/2 + 1]);

    const __half2* kv0 = (const __half2*)(kvh + ((size_t)b) * 2048 + 4*t);
    const __half2* kv1 = (const __half2*)(kvh + ((size_t)BATCH + b) * 2048 + 4*t);
    const __half2* kv2 = (const __half2*)(kvh + ((size_t)2*BATCH + b) * 2048 + 4*t);

    float2 ka0 = __half22float2(kv0[0]), ka1 = __half22float2(kv0[1]);
    float2 kb0 = __half22float2(kv1[0]), kb1 = __half22float2(kv1[1]);
    float2 kc0 = __half22float2(kv2[0]), kc1 = __half22float2(kv2[1]);

    float s0 = qa.x*ka0.x + qa.y*ka0.y + qb.x*ka1.x + qb.y*ka1.y;
    float s1 = qa.x*kb0.x + qa.y*kb0.y + qb.x*kb1.x + qb.y*kb1.y;
    float s2 = qa.x*kc0.x + qa.y*kc0.y + qb.x*kc1.x + qb.y*kc1.y;

    #pragma unroll
    for (int o = 8; o; o >>= 1) {
        s0 += __shfl_xor_sync(0xffffffffu, s0, o, 16);
        s1 += __shfl_xor_sync(0xffffffffu, s1, o, 16);
        s2 += __shfl_xor_sync(0xffffffffu, s2, o, 16);
    }
    const float sc = 0.125f;
    s0 *= sc; s1 *= sc; s2 *= sc;
    float mx = fmaxf(s0, fmaxf(s1, s2));
    float e0 = expf(s0 - mx), e1 = expf(s1 - mx), e2 = expf(s2 - mx);
    float inv = 1.0f / (e0 + e1 + e2);
    e0 *= inv; e1 *= inv; e2 *= inv;

    const __half2* va_p = kv0 + 512;
    const __half2* vb_p = kv1 + 512;
    const __half2* vc_p = kv2 + 512;
    float2 va0 = __half22float2(va_p[0]), va1 = __half22float2(va_p[1]);
    float2 vb0 = __half22float2(vb_p[0]), vb1 = __half22float2(vb_p[1]);
    float2 vc0 = __half22float2(vc_p[0]), vc1 = __half22float2(vc_p[1]);

    const __half2* dm = (const __half2*)(Aqdom + (size_t)b * 2048 + 1024 + 4*t);
    float2 d0 = __half22float2(dm[0]);
    float2 d1 = __half22float2(dm[1]);

    float4 r;
    r.x = d0.x + e0*va0.x + e1*vb0.x + e2*vc0.x;
    r.y = d0.y + e0*va0.y + e1*vb0.y + e2*vc0.y;
    r.z = d1.x + e0*va1.x + e1*vb1.x + e2*vc1.x;
    r.w = d1.y + e0*va1.y + e1*vb1.y + e2*vc1.y;

    float sum = r.x + r.y + r.z + r.w;
    float sq  = r.x*r.x + r.y*r.y + r.z*r.z + r.w*r.w;
    #pragma unroll
    for (int o = 16; o; o >>= 1) {
        sum += __shfl_xor_sync(0xffffffffu, sum, o);
        sq  += __shfl_xor_sync(0xffffffffu, sq,  o);
    }
    __shared__ float red[16];
    const int w = t >> 5;
    if ((t & 31) == 0) { red[w] = sum; red[8 + w] = sq; }
    __syncthreads();
    if (t == 0) {
        float a = 0.f, c = 0.f;
        #pragma unroll
        for (int i = 0; i < 8; i++) { a += red[i]; c += red[8 + i]; }
        red[0] = a; red[8] = c;
    }
    __syncthreads();
    sum = red[0]; sq = red[8];

    const float mu  = sum * (1.0f / DIM);
    const float var = sq * (1.0f / DIM) - mu * mu;
    const float rs  = rsqrtf(var + 1e-5f);

    float4 gg = *(const float4*)(gam + 4 * t);
    float4 bb = *(const float4*)(bet + 4 * t);
    float4 b24 = *(const float4*)(b2 + 4 * t);
    float4 xo;
    xo.x = (r.x - mu) * rs * gg.x + bb.x;
    xo.y = (r.y - mu) * rs * gg.y + bb.y;
    xo.z = (r.z - mu) * rs * gg.z + bb.z;
    xo.w = (r.w - mu) * rs * gg.w + bb.w;
    xh[off/2]   = __floats2half2_rn(xo.x, xo.y);
    xh[off/2+1] = __floats2half2_rn(xo.z, xo.w);
    float4 y0;
    y0.x = xo.x + b24.x; y0.y = xo.y + b24.y;
    y0.z = xo.z + b24.z; y0.w = xo.w + b24.w;
    *(float4*)(y + off) = y0;
}

// ---------------- LN2 + 3-logit head + softmax (warp-per-row, 2048 blocks) ---
__global__ __launch_bounds__(256)
void ln2_head_kernel(const float* __restrict__ y,
                     const float* __restrict__ gam, const float* __restrict__ bet,
                     const float* __restrict__ Ww, const float* __restrict__ bw,
                     float* __restrict__ out)
{
    const int lane = threadIdx.x & 31;
    const int row = (blockIdx.x << 3) + (threadIdx.x >> 5);  // 0..16383
    const float bw0 = bw[0], bw1 = bw[1], bw2 = bw[2];

    const float4* yr = (const float4*)(y + (size_t)row * DIM);

    float sum = 0.f, sq = 0.f;
    #pragma unroll
    for (int i = 0; i < 8; i++) {
        float4 v = yr[i * 32 + lane];
        sum += v.x + v.y + v.z + v.w;
        sq  += v.x*v.x + v.y*v.y + v.z*v.z + v.w*v.w;
    }
    #pragma unroll
    for (int o = 16; o; o >>= 1) {
        sum += __shfl_xor_sync(0xffffffffu, sum, o);
        sq  += __shfl_xor_sync(0xffffffffu, sq,  o);
    }
    const float mu  = sum * (1.0f / DIM);
    const float var = sq * (1.0f / DIM) - mu * mu;
    const float rs  = rsqrtf(var + 1e-5f);

    float l0 = 0.f, l1 = 0.f, l2 = 0.f;
    #pragma unroll
    for (int i = 0; i < 8; i++) {
        const int idx = i * 32 + lane;
        float4 v  = yr[idx];
        float4 gg = *(const float4*)(gam + idx * 4);
        float4 bb = *(const float4*)(bet + idx * 4);
        float xn[4];
        xn[0] = (v.x - mu) * rs * gg.x + bb.x;
        xn[1] = (v.y - mu) * rs * gg.y + bb.y;
        xn[2] = (v.z - mu) * rs * gg.z + bb.z;
        xn[3] = (v.w - mu) * rs * gg.w + bb.w;
        #pragma unroll
        for (int e = 0; e < 4; e++) {
            const float* wr = Ww + (size_t)(idx * 4 + e) * 3;
            l0 += xn[e] * wr[0];
            l1 += xn[e] * wr[1];
            l2 += xn[e] * wr[2];
        }
    }
    #pragma unroll
    for (int o = 16; o; o >>= 1) {
        l0 += __shfl_xor_sync(0xffffffffu, l0, o);
        l1 += __shfl_xor_sync(0xffffffffu, l1, o);
        l2 += __shfl_xor_sync(0xffffffffu, l2, o);
    }
    if (lane == 0) {
        float a = l0 + bw0, c = l1 + bw1, d = l2 + bw2;
        float m = fmaxf(a, fmaxf(c, d));
        float e0 = expf(a - m), e1 = expf(c - m), e2 = expf(d - m);
        float inv = 1.0f / (e0 + e1 + e2);
        out[3 * (size_t)row + 0] = e0 * inv;
        out[3 * (size_t)row + 1] = e1 * inv;
        out[3 * (size_t)row + 2] = e2 * inv;
    }
}

// ---------------- launch ----------------------------------------------------
extern "C" void kernel_launch(void* const* d_in, const int* in_sizes, int n_in,
                              void* d_out, int out_size)
{
    const float* m0   = (const float*)d_in[0];
    const float* m1   = (const float*)d_in[1];
    const float* m2   = (const float*)d_in[2];
    const float* dom  = (const float*)d_in[3];
    const float* Wg   = (const float*)d_in[4];
    const float* bg   = (const float*)d_in[5];
    const float* Wq   = (const float*)d_in[6];
    const float* bq   = (const float*)d_in[7];
    const float* Wk   = (const float*)d_in[8];
    const float* bk   = (const float*)d_in[9];
    const float* Wv   = (const float*)d_in[10];
    const float* bv   = (const float*)d_in[11];
    const float* W1   = (const float*)d_in[12];
    const float* b1   = (const float*)d_in[13];
    const float* W2   = (const float*)d_in[14];
    const float* b2   = (const float*)d_in[15];
    const float* gm1  = (const float*)d_in[16];
    const float* bt1  = (const float*)d_in[17];
    const float* gm2  = (const float*)d_in[18];
    const float* bt2  = (const float*)d_in[19];
    const float* Ww   = (const float*)d_in[20];
    const float* bw   = (const float*)d_in[21];
    float* out = (float*)d_out;

    __half *modsh,*Aq,*Bq,*qh,*kvh,*xh,*h1h,*Wkvth,*W1th,*W2th,*Wgf;
    float *bkv,*bq2,*zb,*y;
    cudaGetSymbolAddress((void**)&modsh, g_modsh);
    cudaGetSymbolAddress((void**)&Aq, g_Aq);
    cudaGetSymbolAddress((void**)&Bq, g_Bq);
    cudaGetSymbolAddress((void**)&qh, g_qh);
    cudaGetSymbolAddress((void**)&kvh, g_kvh);
    cudaGetSymbolAddress((void**)&xh, g_xh);
    cudaGetSymbolAddress((void**)&h1h, g_h1h);
    cudaGetSymbolAddress((void**)&Wkvth, g_Wkvth);
    cudaGetSymbolAddress((void**)&W1th, g_W1th);
    cudaGetSymbolAddress((void**)&W2th, g_W2th);
    cudaGetSymbolAddress((void**)&Wgf, g_Wgf);
    cudaGetSymbolAddress((void**)&bkv, g_bkv);
    cudaGetSymbolAddress((void**)&bq2, g_bq2);
    cudaGetSymbolAddress((void**)&zb, g_zb);
    cudaGetSymbolAddress((void**)&y,  g_y);

    cudaFuncSetAttribute(mma_gemm<0,true>, cudaFuncAttributeMaxDynamicSharedMemorySize, SMEM_SZ);
    cudaFuncSetAttribute(mma_gemm<2,true>, cudaFuncAttributeMaxDynamicSharedMemorySize, SMEM_SZ);
    cudaFuncSetAttribute(qkv_gemm,         cudaFuncAttributeMaxDynamicSharedMemorySize, SMEM_SZ);
    cudaFuncSetAttribute(ffn2_gemm,        cudaFuncAttributeMaxDynamicSharedMemorySize, SMEM_SZ);

    // 1. all independent prep
    prep_all<<<29704, 256>>>((const float4*)m0, (const float4*)m1, (const float4*)m2,
                             (const float4*)dom,
                             Wq, Wk, Wv, W1, W2, Wg, bk, bv, bg, bq,
                             modsh, Aq, Bq, Wkvth, W1th, W2th, Wgf, bkv, bq2);

    // 2. Wgq^T = Wq^T @ Wg -> Bq left half
    mma_gemm<0,true><<<dim3(8,8), 256, SMEM_SZ>>>(Bq + 1024, Wgf, zb,
                                                  nullptr, Bq, DIM, 2048, DIM, 2048);

    // 3. merged q + kv GEMMs
    qkv_gemm<<<7168, 256, SMEM_SZ>>>(Aq, Bq, bq2, qh, modsh, Wkvth, bkv, kvh);

    // 4. attention + LN1 (block-per-row) -> xh (fp16), y0 = LN1(x)+b2 (fp32)
    attn_ln1_kernel<<<BATCH, 256>>>((const __half2*)qh, kvh, Aq, gm1, bt1, b2,
                                    y, (__half2*)xh);

    // 5. h1 = relu(x@W1 + b1) -> fp16
    mma_gemm<2,true><<<dim3(FFN/128, BATCH/128), 256, SMEM_SZ>>>(xh, W1th, b1,
                                                                 nullptr, h1h, DIM, DIM, DIM, FFN);
    // 6. y += h1@W2  (split-K atomic accumulate)
    ffn2_gemm<<<2048, 256, SMEM_SZ>>>(h1h, W2th, y);

    // 7. LN2 + head + softmax (warp-per-row, 2048 blocks)
    ln2_head_kernel<<<2048, 256>>>(y, gm2, bt2, Ww, bw, out);
}

// round 14
// speedup vs baseline: 1.0152x; 1.0152x over previous
#include <cuda_runtime.h>
#include <cuda_fp16.h>
#include <stdint.h>
#include <math.h>

#define BATCH 16384
#define DIM   1024
#define FFN   4096

#define NB ((size_t)BATCH * DIM)
#define NF ((size_t)BATCH * FFN)

// ---------------- scratch (static device globals; no runtime allocs) -------
__device__ __half g_modsh[3 * NB];                     // m0|m1|m2 fp16, stacked [3B,1024]
__device__ __half g_Aq[(size_t)BATCH * 2 * DIM];       // [B, 2048] = [mavg | dom] fp16
__device__ __half g_Bq[(size_t)DIM * 2 * DIM];         // [1024, 2048] = [Wgq^T | Wq^T] fp16
__device__ __half g_qh[NB];
__device__ __half g_kvh[3 * (size_t)BATCH * 2 * DIM];  // [3B, 2048]: k|v
__device__ __half g_xh[NB];
__device__ __half g_h1h[NF];
__device__ __half g_Wkvth[(size_t)2*DIM*DIM];          // Wk^T rows 0..1023, Wv^T rows 1024..2047
__device__ __half g_W1th[(size_t)DIM*FFN];
__device__ __half g_W2th[(size_t)DIM*FFN];
__device__ __half g_Wgf[(size_t)DIM*DIM];              // Wg fp16, NO transpose
__device__ float  g_bkv[2 * DIM];
__device__ float  g_bq2[DIM];
__device__ float  g_zb[DIM];                           // zero bias (zero-initialized)
__device__ __half g_yh[NB];                            // y0 = LN1(x)+b2 (fp16), += FFN2 partials

// ---------------- helpers ----------------------------------------------------
__device__ __forceinline__ uint32_t s2u(const void* p) {
    uint32_t a;
    asm("{ .reg .u64 t; cvta.to.shared.u64 t, %1; cvt.u32.u64 %0, t; }" : "=r"(a) : "l"(p));
    return a;
}
__device__ __forceinline__ void cp16(uint32_t s, const void* g) {
    asm volatile("cp.async.cg.shared.global [%0], [%1], 16;" :: "r"(s), "l"(g));
}
#define SWZ(o) ((o) ^ (((o) >> 3) & 0x70))

__device__ __forceinline__ void ldsm4(uint32_t addr, uint32_t* r) {
    asm volatile("ldmatrix.sync.aligned.m8n8.x4.shared.b16 {%0,%1,%2,%3}, [%4];"
        : "=r"(r[0]), "=r"(r[1]), "=r"(r[2]), "=r"(r[3]) : "r"(addr));
}
__device__ __forceinline__ void mma16816(float* c, const uint32_t* a, const uint32_t* b) {
    asm volatile(
        "mma.sync.aligned.m16n8k16.row.col.f32.f16.f16.f32 "
        "{%0,%1,%2,%3}, {%4,%5,%6,%7}, {%8,%9}, {%0,%1,%2,%3};"
        : "+f"(c[0]), "+f"(c[1]), "+f"(c[2]), "+f"(c[3])
        : "r"(a[0]), "r"(a[1]), "r"(a[2]), "r"(a[3]), "r"(b[0]), "r"(b[1]));
}
__device__ __forceinline__ void redadd_h2(__half2* p, __half2 v) {
    asm volatile("red.global.add.noftz.f16x2 [%0], %1;"
        :: "l"(p), "r"(*(const uint32_t*)&v) : "memory");
}

// ---------------- GEMM body (128x128 CTA, 32x64 warp tiles) ------------------
#define STAGE_SZ 32768
#define SMEM_SZ  (3 * STAGE_SZ)

__device__ __forceinline__ void ldtile(uint32_t sbase, const __half* g, int ldk, int tid) {
    #pragma unroll
    for (int i = 0; i < 4; i++) {
        int idx = tid + (i << 8);
        int row = idx >> 3, ks = idx & 7;
        cp16(sbase + SWZ(row * 128 + ks * 16), g + (size_t)row * ldk + ks * 8);
    }
}

// MODE 0: +bias, write fp16; MODE 2: relu(+bias), write fp16;
// MODE 3: fp16x2 atomic accumulate into Dh (no bias)
template<int MODE>
__device__ __forceinline__ void gemm_body(
    const __half* __restrict__ A, const __half* __restrict__ B,
    const float* __restrict__ bias, __half* __restrict__ Dh,
    int bm, int bn, int K, int lda, int ldb, int ldd, uint32_t sb)
{
    const int tid = threadIdx.x;
    const int wid = tid >> 5, lane = tid & 31;
    const int wm = (wid >> 1) << 5;
    const int wn = (wid & 1) << 6;
    const int nch = K >> 6;

    const __half* Ap = A + (size_t)bm * lda;
    const __half* Bp = B + (size_t)bn * ldb;

    #pragma unroll
    for (int c = 0; c < 2; c++) {
        uint32_t st = sb + c * STAGE_SZ;
        ldtile(st,         Ap + c * 64, lda, tid);
        ldtile(st + 16384, Bp + c * 64, ldb, tid);
        asm volatile("cp.async.commit_group;" ::: "memory");
    }

    float acc[2][8][4];
    #pragma unroll
    for (int a = 0; a < 2; a++)
        #pragma unroll
        for (int b2 = 0; b2 < 8; b2++)
            #pragma unroll
            for (int d = 0; d < 4; d++) acc[a][b2][d] = 0.0f;

    const int aRow = wm + (lane & 15);
    const int aKB  = ((lane >> 4) & 1) * 16;
    const int bj   = lane >> 3;
    const int bRow = wn + ((bj >> 1) << 3) + (lane & 7);
    const int bKB  = (bj & 1) * 16;

    for (int i = 0; i < nch; i++) {
        if (i < nch - 1) asm volatile("cp.async.wait_group 1;" ::: "memory");
        else             asm volatile("cp.async.wait_group 0;" ::: "memory");
        __syncthreads();

        const int pc = i + 2;
        if (pc < nch) {
            uint32_t pt = sb + (pc % 3) * STAGE_SZ;
            ldtile(pt,         Ap + pc * 64, lda, tid);
            ldtile(pt + 16384, Bp + pc * 64, ldb, tid);
            asm volatile("cp.async.commit_group;" ::: "memory");
        }

        const uint32_t st = sb + (i % 3) * STAGE_SZ;
        #pragma unroll
        for (int kk = 0; kk < 4; kk++) {
            uint32_t aR[2][4];
            #pragma unroll
            for (int tm = 0; tm < 2; tm++) {
                uint32_t off = SWZ((uint32_t)((aRow + tm * 16) * 128 + kk * 32 + aKB));
                ldsm4(st + off, aR[tm]);
            }
            uint32_t bR[4][4];
            #pragma unroll
            for (int p = 0; p < 4; p++) {
                uint32_t off = SWZ((uint32_t)((bRow + p * 16) * 128 + kk * 32 + bKB));
                ldsm4(st + 16384 + off, bR[p]);
            }
            #pragma unroll
            for (int tm = 0; tm < 2; tm++)
                #pragma unroll
                for (int p = 0; p < 4; p++) {
                    mma16816(acc[tm][2*p],     aR[tm], &bR[p][0]);
                    mma16816(acc[tm][2*p + 1], aR[tm], &bR[p][2]);
                }
        }
    }

    const int lm = lane >> 2, lc = (lane & 3) << 1;
    float2 bs[8];
    if (MODE != 3) {
        #pragma unroll
        for (int nt = 0; nt < 8; nt++)
            bs[nt] = *(const float2*)(bias + bn + wn + nt * 8 + lc);
    }

    #pragma unroll
    for (int tm = 0; tm < 2; tm++)
        #pragma unroll
        for (int g = 0; g < 2; g++) {
            const int row = bm + wm + tm * 16 + g * 8 + lm;
            #pragma unroll
            for (int nt = 0; nt < 8; nt++) {
                const int col = bn + wn + nt * 8 + lc;
                float v0 = acc[tm][nt][g * 2 + 0];
                float v1 = acc[tm][nt][g * 2 + 1];
                if (MODE == 3) {
                    redadd_h2((__half2*)(Dh + (size_t)row * ldd + col),
                              __floats2half2_rn(v0, v1));
                    continue;
                }
                v0 += bs[nt].x; v1 += bs[nt].y;
                if (MODE == 2) { v0 = fmaxf(v0, 0.f); v1 = fmaxf(v1, 0.f); }
                *(__half2*)(Dh + (size_t)row * ldd + col) = __floats2half2_rn(v0, v1);
            }
        }
}

template<int MODE>
__global__ __launch_bounds__(256, 2)
void mma_gemm(const __half* __restrict__ A, const __half* __restrict__ B,
              const float* __restrict__ bias, __half* __restrict__ Dh,
              int K, int lda, int ldb, int ldd)
{
    extern __shared__ char smem[];
    gemm_body<MODE>(A, B, bias, Dh,
                    blockIdx.y << 7, blockIdx.x << 7, K, lda, ldb, ldd, s2u(smem));
}

// merged q-GEMM (blocks 0..1023) + kv-GEMM (blocks 1024..7167)
__global__ __launch_bounds__(256, 2)
void qkv_gemm(const __half* __restrict__ Aq, const __half* __restrict__ Bq,
              const float* __restrict__ bq2, __half* __restrict__ qh,
              const __half* __restrict__ mods, const __half* __restrict__ Wkv,
              const float* __restrict__ bkv, __half* __restrict__ kvh)
{
    extern __shared__ char smem[];
    uint32_t sb = s2u(smem);
    int b = blockIdx.x;
    if (b < 1024) {
        gemm_body<0>(Aq, Bq, bq2, qh,
                     (b >> 3) << 7, (b & 7) << 7, 2048, 2048, 2048, 1024, sb);
    } else {
        b -= 1024;
        gemm_body<0>(mods, Wkv, bkv, kvh,
                     (b >> 4) << 7, (b & 15) << 7, 1024, 1024, 1024, 2048, sb);
    }
}

// FFN2 split-K: 2048 CTAs, K halves of 2048, fp16x2 atomic-accumulate into y
__global__ __launch_bounds__(256, 2)
void ffn2_gemm(const __half* __restrict__ h1, const __half* __restrict__ W2t,
               __half* __restrict__ y)
{
    extern __shared__ char smem[];
    int b = blockIdx.x;
    const int kp = b >> 10;          // 0 or 1
    b &= 1023;
    gemm_body<3>(h1 + (size_t)kp * 2048, W2t + (size_t)kp * 2048, nullptr, y,
                 (b >> 3) << 7, (b & 7) << 7, 2048, FFN, FFN, DIM, s2u(smem));
}

// ---------------- fused prep: activations + all weight prep ------------------
__device__ __forceinline__ void wtrans_body(const float* __restrict__ W, __half* __restrict__ H,
                                            int N, int ldh, int bx, int by,
                                            float (*t)[33], int tx, int ty)
{
    const int k0 = by << 5, n0 = bx << 5;
    #pragma unroll
    for (int r = 0; r < 32; r += 8)
        t[ty + r][tx] = W[(size_t)(k0 + ty + r) * N + n0 + tx];
    __syncthreads();
    #pragma unroll
    for (int r = 0; r < 32; r += 8)
        H[(size_t)(n0 + ty + r) * ldh + k0 + tx] = __float2half(t[tx][ty + r]);
}

__global__ __launch_bounds__(256)
void prep_all(const float4* __restrict__ m0, const float4* __restrict__ m1,
              const float4* __restrict__ m2, const float4* __restrict__ dom,
              const float* __restrict__ Wq, const float* __restrict__ Wk,
              const float* __restrict__ Wv, const float* __restrict__ W1f,
              const float* __restrict__ W2f, const float* __restrict__ Wg,
              const float* __restrict__ bk, const float* __restrict__ bv,
              const float* __restrict__ bg, const float* __restrict__ bq,
              __half* __restrict__ mods, __half* __restrict__ Aq, __half* __restrict__ Bq,
              __half* __restrict__ Wkvth, __half* __restrict__ W1th, __half* __restrict__ W2th,
              __half* __restrict__ Wgf, float* __restrict__ bkv, float* __restrict__ bq2)
{
    __shared__ float t[32][33];
    const int b = blockIdx.x;
    const int tid = threadIdx.x;
    const int tx = tid & 31, ty = tid >> 5;

    if (b < 16384) {
        const int i = b * 256 + tid;
        float4 a = m0[i], bb = m1[i], c = m2[i], d = dom[i];
        const float s = 1.0f / 3.0f;
        const int r = i >> 8, c4 = (i & 255) << 2;
        const size_t nbh = NB;
        __half2* modsp = (__half2*)mods;
        modsp[(0*nbh + (size_t)r*1024 + c4) >> 1]       = __floats2half2_rn(a.x, a.y);
        modsp[((0*nbh + (size_t)r*1024 + c4) >> 1) + 1] = __floats2half2_rn(a.z, a.w);
        modsp[(1*nbh + (size_t)r*1024 + c4) >> 1]       = __floats2half2_rn(bb.x, bb.y);
        modsp[((1*nbh + (size_t)r*1024 + c4) >> 1) + 1] = __floats2half2_rn(bb.z, bb.w);
        modsp[(2*nbh + (size_t)r*1024 + c4) >> 1]       = __floats2half2_rn(c.x, c.y);
        modsp[((2*nbh + (size_t)r*1024 + c4) >> 1) + 1] = __floats2half2_rn(c.z, c.w);
        float4 v;
        v.x = (a.x+bb.x+c.x)*s; v.y = (a.y+bb.y+c.y)*s;
        v.z = (a.z+bb.z+c.z)*s; v.w = (a.w+bb.w+c.w)*s;
        __half2* aqp = (__half2*)(Aq + (size_t)r * 2048 + c4);
        aqp[0] = __floats2half2_rn(v.x, v.y);
        aqp[1] = __floats2half2_rn(v.z, v.w);
        __half2* aqd = (__half2*)(Aq + (size_t)r * 2048 + 1024 + c4);
        aqd[0] = __floats2half2_rn(d.x, d.y);
        aqd[1] = __floats2half2_rn(d.z, d.w);
    } else if (b < 17408) {
        int bl = b - 16384;
        wtrans_body(Wq, Bq + 1024, DIM, 2048, bl & 31, bl >> 5, t, tx, ty);
    } else if (b < 18432) {
        int bl = b - 17408;
        wtrans_body(Wk, Wkvth, DIM, DIM, bl & 31, bl >> 5, t, tx, ty);
    } else if (b < 19456) {
        int bl = b - 18432;
        wtrans_body(Wv, Wkvth + (size_t)DIM * DIM, DIM, DIM, bl & 31, bl >> 5, t, tx, ty);
    } else if (b < 23552) {
        int bl = b - 19456;
        wtrans_body(W1f, W1th, FFN, DIM, bl & 127, bl >> 7, t, tx, ty);
    } else if (b < 27648) {
        int bl = b - 23552;
        wtrans_body(W2f, W2th, DIM, FFN, bl & 31, bl >> 5, t, tx, ty);
    } else if (b < 28672) {
        int i = (b - 27648) * 1024 + tid * 4;
        float4 w = *(const float4*)(Wg + i);
        __half2* o = (__half2*)(Wgf + i);
        o[0] = __floats2half2_rn(w.x, w.y);
        o[1] = __floats2half2_rn(w.z, w.w);
    } else if (b < 28680) {
        int i = (b - 28672) * 256 + tid;
        bkv[i]       = bk[i];
        bkv[i + DIM] = bv[i];
    } else {
        int n = b - 28680;
        float s = 0.f;
        for (int k = tid; k < DIM; k += 256) s += bg[k] * Wq[(size_t)k * DIM + n];
        #pragma unroll
        for (int o = 16; o; o >>= 1) s += __shfl_xor_sync(0xffffffffu, s, o);
        float* red = &t[0][0];
        if ((tid & 31) == 0) red[tid >> 5] = s;
        __syncthreads();
        if (tid == 0) {
            float a = 0.f;
            #pragma unroll
            for (int i = 0; i < 8; i++) a += red[i];
            bq2[n] = a + bq[n];
        }
    }
}

// ---------------- attention + residual + LN1 (block-per-row) -----------------
__global__ __launch_bounds__(256)
void attn_ln1_kernel(const __half2* __restrict__ qh,
                     const __half* __restrict__ kvh,
                     const __half* __restrict__ Aqdom,
                     const float* __restrict__ gam, const float* __restrict__ bet,
                     const float* __restrict__ b2,
                     __half2* __restrict__ yh, __half2* __restrict__ xh)
{
    const int b = blockIdx.x;
    const int t = threadIdx.x;
    const size_t off = (size_t)b * DIM + 4 * t;

    float2 qa = __half22float2(qh[off/2]);
    float2 qb = __half22float2(qh[off/2 + 1]);

    const __half2* kv0 = (const __half2*)(kvh + ((size_t)b) * 2048 + 4*t);
    const __half2* kv1 = (const __half2*)(kvh + ((size_t)BATCH + b) * 2048 + 4*t);
    const __half2* kv2 = (const __half2*)(kvh + ((size_t)2*BATCH + b) * 2048 + 4*t);

    float2 ka0 = __half22float2(kv0[0]), ka1 = __half22float2(kv0[1]);
    float2 kb0 = __half22float2(kv1[0]), kb1 = __half22float2(kv1[1]);
    float2 kc0 = __half22float2(kv2[0]), kc1 = __half22float2(kv2[1]);

    float s0 = qa.x*ka0.x + qa.y*ka0.y + qb.x*ka1.x + qb.y*ka1.y;
    float s1 = qa.x*kb0.x + qa.y*kb0.y + qb.x*kb1.x + qb.y*kb1.y;
    float s2 = qa.x*kc0.x + qa.y*kc0.y + qb.x*kc1.x + qb.y*kc1.y;

    #pragma unroll
    for (int o = 8; o; o >>= 1) {
        s0 += __shfl_xor_sync(0xffffffffu, s0, o, 16);
        s1 += __shfl_xor_sync(0xffffffffu, s1, o, 16);
        s2 += __shfl_xor_sync(0xffffffffu, s2, o, 16);
    }
    const float sc = 0.125f;
    s0 *= sc; s1 *= sc; s2 *= sc;
    float mx = fmaxf(s0, fmaxf(s1, s2));
    float e0 = expf(s0 - mx), e1 = expf(s1 - mx), e2 = expf(s2 - mx);
    float inv = 1.0f / (e0 + e1 + e2);
    e0 *= inv; e1 *= inv; e2 *= inv;

    const __half2* va_p = kv0 + 512;
    const __half2* vb_p = kv1 + 512;
    const __half2* vc_p = kv2 + 512;
    float2 va0 = __half22float2(va_p[0]), va1 = __half22float2(va_p[1]);
    float2 vb0 = __half22float2(vb_p[0]), vb1 = __half22float2(vb_p[1]);
    float2 vc0 = __half22float2(vc_p[0]), vc1 = __half22float2(vc_p[1]);

    const __half2* dm = (const __half2*)(Aqdom + (size_t)b * 2048 + 1024 + 4*t);
    float2 d0 = __half22float2(dm[0]);
    float2 d1 = __half22float2(dm[1]);

    float4 r;
    r.x = d0.x + e0*va0.x + e1*vb0.x + e2*vc0.x;
    r.y = d0.y + e0*va0.y + e1*vb0.y + e2*vc0.y;
    r.z = d1.x + e0*va1.x + e1*vb1.x + e2*vc1.x;
    r.w = d1.y + e0*va1.y + e1*vb1.y + e2*vc1.y;

    float sum = r.x + r.y + r.z + r.w;
    float sq  = r.x*r.x + r.y*r.y + r.z*r.z + r.w*r.w;
    #pragma unroll
    for (int o = 16; o; o >>= 1) {
        sum += __shfl_xor_sync(0xffffffffu, sum, o);
        sq  += __shfl_xor_sync(0xffffffffu, sq,  o);
    }
    __shared__ float red[16];
    const int w = t >> 5;
    if ((t & 31) == 0) { red[w] = sum; red[8 + w] = sq; }
    __syncthreads();
    if (t == 0) {
        float a = 0.f, c = 0.f;
        #pragma unroll
        for (int i = 0; i < 8; i++) { a += red[i]; c += red[8 + i]; }
        red[0] = a; red[8] = c;
    }
    __syncthreads();
    sum = red[0]; sq = red[8];

    const float mu  = sum * (1.0f / DIM);
    const float var = sq * (1.0f / DIM) - mu * mu;
    const float rs  = rsqrtf(var + 1e-5f);

    float4 gg = *(const float4*)(gam + 4 * t);
    float4 bb = *(const float4*)(bet + 4 * t);
    float4 b24 = *(const float4*)(b2 + 4 * t);
    float4 xo;
    xo.x = (r.x - mu) * rs * gg.x + bb.x;
    xo.y = (r.y - mu) * rs * gg.y + bb.y;
    xo.z = (r.z - mu) * rs * gg.z + bb.z;
    xo.w = (r.w - mu) * rs * gg.w + bb.w;
    xh[off/2]   = __floats2half2_rn(xo.x, xo.y);
    xh[off/2+1] = __floats2half2_rn(xo.z, xo.w);
    yh[off/2]   = __floats2half2_rn(xo.x + b24.x, xo.y + b24.y);
    yh[off/2+1] = __floats2half2_rn(xo.z + b24.z, xo.w + b24.w);
}

// ---------------- LN2 + 3-logit head + softmax (warp-per-row, fp16 y) --------
__global__ __launch_bounds__(256)
void ln2_head_kernel(const __half* __restrict__ y,
                     const float* __restrict__ gam, const float* __restrict__ bet,
                     const float* __restrict__ Ww, const float* __restrict__ bw,
                     float* __restrict__ out)
{
    const int lane = threadIdx.x & 31;
    const int gw = (blockIdx.x << 3) + (threadIdx.x >> 5);  // 0..4095
    const float bw0 = bw[0], bw1 = bw[1], bw2 = bw[2];

    #pragma unroll
    for (int rr = 0; rr < 4; rr++) {
        const int row = (gw << 2) + rr;
        const uint4* yr = (const uint4*)(y + (size_t)row * DIM);   // 128 uint4/row

        float sum = 0.f, sq = 0.f;
        float vv[4][8];
        #pragma unroll
        for (int i = 0; i < 4; i++) {
            uint4 u = yr[i * 32 + lane];
            const __half2* h = (const __half2*)&u;
            #pragma unroll
            for (int k = 0; k < 4; k++) {
                float2 f = __half22float2(h[k]);
                vv[i][2*k]   = f.x;
                vv[i][2*k+1] = f.y;
                sum += f.x + f.y;
                sq  += f.x*f.x + f.y*f.y;
            }
        }
        #pragma unroll
        for (int o = 16; o; o >>= 1) {
            sum += __shfl_xor_sync(0xffffffffu, sum, o);
            sq  += __shfl_xor_sync(0xffffffffu, sq,  o);
        }
        const float mu  = sum * (1.0f / DIM);
        const float var = sq * (1.0f / DIM) - mu * mu;
        const float rs  = rsqrtf(var + 1e-5f);

        float l0 = 0.f, l1 = 0.f, l2 = 0.f;
        #pragma unroll
        for (int i = 0; i < 4; i++) {
            const int base = (i * 32 + lane) * 8;
            float4 g0 = *(const float4*)(gam + base);
            float4 g1 = *(const float4*)(gam + base + 4);
            float4 bb0 = *(const float4*)(bet + base);
            float4 bb1 = *(const float4*)(bet + base + 4);
            float xn[8];
            xn[0] = (vv[i][0] - mu) * rs * g0.x + bb0.x;
            xn[1] = (vv[i][1] - mu) * rs * g0.y + bb0.y;
            xn[2] = (vv[i][2] - mu) * rs * g0.z + bb0.z;
            xn[3] = (vv[i][3] - mu) * rs * g0.w + bb0.w;
            xn[4] = (vv[i][4] - mu) * rs * g1.x + bb1.x;
            xn[5] = (vv[i][5] - mu) * rs * g1.y + bb1.y;
            xn[6] = (vv[i][6] - mu) * rs * g1.z + bb1.z;
            xn[7] = (vv[i][7] - mu) * rs * g1.w + bb1.w;
            #pragma unroll
            for (int e = 0; e < 8; e++) {
                const float* wr = Ww + (size_t)(base + e) * 3;
                l0 += xn[e] * wr[0];
                l1 += xn[e] * wr[1];
                l2 += xn[e] * wr[2];
            }
        }
        #pragma unroll
        for (int o = 16; o; o >>= 1) {
            l0 += __shfl_xor_sync(0xffffffffu, l0, o);
            l1 += __shfl_xor_sync(0xffffffffu, l1, o);
            l2 += __shfl_xor_sync(0xffffffffu, l2, o);
        }
        if (lane == 0) {
            float a = l0 + bw0, c = l1 + bw1, d = l2 + bw2;
            float m = fmaxf(a, fmaxf(c, d));
            float e0 = expf(a - m), e1 = expf(c - m), e2 = expf(d - m);
            float inv = 1.0f / (e0 + e1 + e2);
            out[3 * (size_t)row + 0] = e0 * inv;
            out[3 * (size_t)row + 1] = e1 * inv;
            out[3 * (size_t)row + 2] = e2 * inv;
        }
    }
}

// ---------------- launch ----------------------------------------------------
extern "C" void kernel_launch(void* const* d_in, const int* in_sizes, int n_in,
                              void* d_out, int out_size)
{
    const float* m0   = (const float*)d_in[0];
    const float* m1   = (const float*)d_in[1];
    const float* m2   = (const float*)d_in[2];
    const float* dom  = (const float*)d_in[3];
    const float* Wg   = (const float*)d_in[4];
    const float* bg   = (const float*)d_in[5];
    const float* Wq   = (const float*)d_in[6];
    const float* bq   = (const float*)d_in[7];
    const float* Wk   = (const float*)d_in[8];
    const float* bk   = (const float*)d_in[9];
    const float* Wv   = (const float*)d_in[10];
    const float* bv   = (const float*)d_in[11];
    const float* W1   = (const float*)d_in[12];
    const float* b1   = (const float*)d_in[13];
    const float* W2   = (const float*)d_in[14];
    const float* b2   = (const float*)d_in[15];
    const float* gm1  = (const float*)d_in[16];
    const float* bt1  = (const float*)d_in[17];
    const float* gm2  = (const float*)d_in[18];
    const float* bt2  = (const float*)d_in[19];
    const float* Ww   = (const float*)d_in[20];
    const float* bw   = (const float*)d_in[21];
    float* out = (float*)d_out;

    __half *modsh,*Aq,*Bq,*qh,*kvh,*xh,*h1h,*Wkvth,*W1th,*W2th,*Wgf,*yh;
    float *bkv,*bq2,*zb;
    cudaGetSymbolAddress((void**)&modsh, g_modsh);
    cudaGetSymbolAddress((void**)&Aq, g_Aq);
    cudaGetSymbolAddress((void**)&Bq, g_Bq);
    cudaGetSymbolAddress((void**)&qh, g_qh);
    cudaGetSymbolAddress((void**)&kvh, g_kvh);
    cudaGetSymbolAddress((void**)&xh, g_xh);
    cudaGetSymbolAddress((void**)&h1h, g_h1h);
    cudaGetSymbolAddress((void**)&Wkvth, g_Wkvth);
    cudaGetSymbolAddress((void**)&W1th, g_W1th);
    cudaGetSymbolAddress((void**)&W2th, g_W2th);
    cudaGetSymbolAddress((void**)&Wgf, g_Wgf);
    cudaGetSymbolAddress((void**)&bkv, g_bkv);
    cudaGetSymbolAddress((void**)&bq2, g_bq2);
    cudaGetSymbolAddress((void**)&zb, g_zb);
    cudaGetSymbolAddress((void**)&yh, g_yh);

    cudaFuncSetAttribute(mma_gemm<0>, cudaFuncAttributeMaxDynamicSharedMemorySize, SMEM_SZ);
    cudaFuncSetAttribute(mma_gemm<2>, cudaFuncAttributeMaxDynamicSharedMemorySize, SMEM_SZ);
    cudaFuncSetAttribute(qkv_gemm,    cudaFuncAttributeMaxDynamicSharedMemorySize, SMEM_SZ);
    cudaFuncSetAttribute(ffn2_gemm,   cudaFuncAttributeMaxDynamicSharedMemorySize, SMEM_SZ);

    // 1. all independent prep
    prep_all<<<29704, 256>>>((const float4*)m0, (const float4*)m1, (const float4*)m2,
                             (const float4*)dom,
                             Wq, Wk, Wv, W1, W2, Wg, bk, bv, bg, bq,
                             modsh, Aq, Bq, Wkvth, W1th, W2th, Wgf, bkv, bq2);

    // 2. Wgq^T = Wq^T @ Wg -> Bq left half
    mma_gemm<0><<<dim3(8,8), 256, SMEM_SZ>>>(Bq + 1024, Wgf, zb, Bq, DIM, 2048, DIM, 2048);

    // 3. merged q + kv GEMMs
    qkv_gemm<<<7168, 256, SMEM_SZ>>>(Aq, Bq, bq2, qh, modsh, Wkvth, bkv, kvh);

    // 4. attention + LN1 (block-per-row) -> xh (fp16), y0 = LN1(x)+b2 (fp16)
    attn_ln1_kernel<<<BATCH, 256>>>((const __half2*)qh, kvh, Aq, gm1, bt1, b2,
                                    (__half2*)yh, (__half2*)xh);

    // 5. h1 = relu(x@W1 + b1) -> fp16
    mma_gemm<2><<<dim3(FFN/128, BATCH/128), 256, SMEM_SZ>>>(xh, W1th, b1, h1h,
                                                            DIM, DIM, DIM, FFN);
    // 6. y += h1@W2  (split-K fp16x2 atomic accumulate)
    ffn2_gemm<<<2048, 256, SMEM_SZ>>>(h1h, W2th, yh);

    // 7. LN2 + head + softmax (warp-per-row, fp16 y)
    ln2_head_kernel<<<512, 256>>>(yh, gm2, bt2, Ww, bw, out);
}